// round 1
// baseline (speedup 1.0000x reference)
#include <cuda_runtime.h>
#include <cstdint>

#define NH     16
#define DH     64
#define LSEQ   1024
#define NB     4
#define DMODEL 1024
#define NPOS   257
#define BH     (NB*NH)       // 64
#define ROWS   (BH*LSEQ)     // 65536
#define MROW   (NB*LSEQ)     // 4096

// ---------------- scratch (device globals; no allocation allowed) ----------
__device__ float g_Q[(size_t)ROWS*DH];        // [B,H,L,d]
__device__ float g_K[(size_t)ROWS*DH];
__device__ float g_V[(size_t)ROWS*DH];
__device__ float g_R[(size_t)ROWS*NPOS];      // Q . posK^T
__device__ float g_T[(size_t)ROWS*NPOS];      // scattered A
__device__ float g_S[(size_t)ROWS*LSEQ];      // scores / attn probs (268MB)
__device__ float g_O[(size_t)MROW*DMODEL];    // (O1+O2) in [B,L,D] layout

// ---------------- 128x128x8 fp32 GEMM: C = A@W + bias ----------------------
// HEADMAJOR: write C at [((b*H+h)*L + l)*64 + dd] instead of row-major.
template<bool HEADMAJOR>
__global__ void __launch_bounds__(256) gemm_proj(
    const float* __restrict__ A, const float* __restrict__ W,
    const float* __restrict__ bias, float* __restrict__ C,
    int M, int N, int K)
{
    __shared__ float As[8][128];
    __shared__ float Bs[8][128];
    int tid = threadIdx.x;
    int bm = blockIdx.y * 128, bn = blockIdx.x * 128;
    int tx = tid & 15, ty = tid >> 4;

    float acc[8][8];
#pragma unroll
    for (int i = 0; i < 8; i++)
#pragma unroll
        for (int j = 0; j < 8; j++) acc[i][j] = 0.f;

    int arow = tid >> 1, ac4 = (tid & 1) * 4;
    int brow = tid >> 5, bc4 = (tid & 31) * 4;
    const float* Aptr = A + (size_t)(bm + arow) * K + ac4;
    const float* Bptr = W + (size_t)brow * N + bn + bc4;

    for (int k0 = 0; k0 < K; k0 += 8) {
        float4 av = *(const float4*)(Aptr + k0);
        As[ac4 + 0][arow] = av.x;
        As[ac4 + 1][arow] = av.y;
        As[ac4 + 2][arow] = av.z;
        As[ac4 + 3][arow] = av.w;
        float4 bv = *(const float4*)(Bptr + (size_t)k0 * N);
        *(float4*)&Bs[brow][bc4] = bv;
        __syncthreads();
#pragma unroll
        for (int kk = 0; kk < 8; kk++) {
            float a[8], b[8];
            *(float4*)(a)     = *(const float4*)&As[kk][ty * 8];
            *(float4*)(a + 4) = *(const float4*)&As[kk][ty * 8 + 4];
            *(float4*)(b)     = *(const float4*)&Bs[kk][tx * 8];
            *(float4*)(b + 4) = *(const float4*)&Bs[kk][tx * 8 + 4];
#pragma unroll
            for (int i = 0; i < 8; i++)
#pragma unroll
                for (int j = 0; j < 8; j++) acc[i][j] += a[i] * b[j];
        }
        __syncthreads();
    }

#pragma unroll
    for (int i = 0; i < 8; i++) {
        int r = bm + ty * 8 + i;
#pragma unroll
        for (int j = 0; j < 8; j++) {
            int c = bn + tx * 8 + j;
            float v = acc[i][j] + bias[c];
            if (HEADMAJOR) {
                int b = r >> 10, l = r & 1023, h = c >> 6, dd = c & 63;
                C[(((size_t)(b * NH + h) * LSEQ + l) << 6) + dd] = v;
            } else {
                C[(size_t)r * N + c] = v;
            }
        }
    }
}

// ---------------- R = Q @ posK^T  (M=65536, N=257, K=64) -------------------
__global__ void __launch_bounds__(256) gemm_qposk(const float* __restrict__ posK)
{
    __shared__ float As[16][64];
    __shared__ float Bs[16][64];
    int tid = threadIdx.x, tx = tid & 15, ty = tid >> 4;
    int bm = blockIdx.y * 64, bn = blockIdx.x * 64;
    float acc[4][4];
#pragma unroll
    for (int i = 0; i < 4; i++)
#pragma unroll
        for (int j = 0; j < 4; j++) acc[i][j] = 0.f;

    int lrow = tid >> 2, lc4 = (tid & 3) * 4;
    for (int k0 = 0; k0 < 64; k0 += 16) {
        float4 av = *(const float4*)&g_Q[(size_t)(bm + lrow) * 64 + k0 + lc4];
        As[lc4 + 0][lrow] = av.x; As[lc4 + 1][lrow] = av.y;
        As[lc4 + 2][lrow] = av.z; As[lc4 + 3][lrow] = av.w;
        int n = bn + lrow;
        float4 bv = make_float4(0.f, 0.f, 0.f, 0.f);
        if (n < NPOS) bv = *(const float4*)&posK[(size_t)n * 64 + k0 + lc4];
        Bs[lc4 + 0][lrow] = bv.x; Bs[lc4 + 1][lrow] = bv.y;
        Bs[lc4 + 2][lrow] = bv.z; Bs[lc4 + 3][lrow] = bv.w;
        __syncthreads();
#pragma unroll
        for (int kk = 0; kk < 16; kk++) {
            float a[4], b[4];
            *(float4*)a = *(const float4*)&As[kk][ty * 4];
            *(float4*)b = *(const float4*)&Bs[kk][tx * 4];
#pragma unroll
            for (int i = 0; i < 4; i++)
#pragma unroll
                for (int j = 0; j < 4; j++) acc[i][j] += a[i] * b[j];
        }
        __syncthreads();
    }
#pragma unroll
    for (int i = 0; i < 4; i++) {
        int r = bm + ty * 4 + i;
#pragma unroll
        for (int j = 0; j < 4; j++) {
            int n = bn + tx * 4 + j;
            if (n < NPOS) g_R[(size_t)r * NPOS + n] = acc[i][j];
        }
    }
}

// ------- S = (Q K^T + gather(R)) * 0.125 * pad,  batched over bh -----------
__global__ void __launch_bounds__(256) attn_scores(const float* __restrict__ pad)
{
    __shared__ float Qs[16][64];
    __shared__ float Ks[16][64];
    int z = blockIdx.z;
    const float* Qp = g_Q + (size_t)z * LSEQ * DH;
    const float* Kp = g_K + (size_t)z * LSEQ * DH;
    int bm = blockIdx.y * 64, bn = blockIdx.x * 64;
    int tid = threadIdx.x, tx = tid & 15, ty = tid >> 4;
    float acc[4][4];
#pragma unroll
    for (int i = 0; i < 4; i++)
#pragma unroll
        for (int j = 0; j < 4; j++) acc[i][j] = 0.f;

    int lrow = tid >> 2, lc4 = (tid & 3) * 4;
    for (int k0 = 0; k0 < 64; k0 += 16) {
        float4 qv = *(const float4*)&Qp[(size_t)(bm + lrow) * 64 + k0 + lc4];
        Qs[lc4 + 0][lrow] = qv.x; Qs[lc4 + 1][lrow] = qv.y;
        Qs[lc4 + 2][lrow] = qv.z; Qs[lc4 + 3][lrow] = qv.w;
        float4 kv = *(const float4*)&Kp[(size_t)(bn + lrow) * 64 + k0 + lc4];
        Ks[lc4 + 0][lrow] = kv.x; Ks[lc4 + 1][lrow] = kv.y;
        Ks[lc4 + 2][lrow] = kv.z; Ks[lc4 + 3][lrow] = kv.w;
        __syncthreads();
#pragma unroll
        for (int kk = 0; kk < 16; kk++) {
            float a[4], b[4];
            *(float4*)a = *(const float4*)&Qs[kk][ty * 4];
            *(float4*)b = *(const float4*)&Ks[kk][tx * 4];
#pragma unroll
            for (int i = 0; i < 4; i++)
#pragma unroll
                for (int j = 0; j < 4; j++) acc[i][j] += a[i] * b[j];
        }
        __syncthreads();
    }
    int b = z >> 4;
#pragma unroll
    for (int i = 0; i < 4; i++) {
        int q = bm + ty * 4 + i;
#pragma unroll
        for (int j = 0; j < 4; j++) {
            int kp = bn + tx * 4 + j;
            int dlt = kp - q;
            dlt = min(max(dlt, -128), 128);
            float r2 = g_R[((size_t)z * LSEQ + q) * NPOS + dlt + 128];
            g_S[((size_t)z * LSEQ + q) * LSEQ + kp] =
                (acc[i][j] + r2) * 0.125f * pad[b * LSEQ + kp];
        }
    }
}

// ---------------- softmax over last axis, in-place -------------------------
__global__ void __launch_bounds__(256) softmax_k()
{
    int row = blockIdx.x;
    float* S = g_S + (size_t)row * LSEQ;
    int tid = threadIdx.x;
    __shared__ float red[256];
    float4 v = *(float4*)&S[tid * 4];
    float m = fmaxf(fmaxf(v.x, v.y), fmaxf(v.z, v.w));
    red[tid] = m; __syncthreads();
    for (int s = 128; s > 0; s >>= 1) {
        if (tid < s) red[tid] = fmaxf(red[tid], red[tid + s]);
        __syncthreads();
    }
    m = red[0]; __syncthreads();
    v.x = __expf(v.x - m); v.y = __expf(v.y - m);
    v.z = __expf(v.z - m); v.w = __expf(v.w - m);
    red[tid] = v.x + v.y + v.z + v.w; __syncthreads();
    for (int s = 128; s > 0; s >>= 1) {
        if (tid < s) red[tid] += red[tid + s];
        __syncthreads();
    }
    float inv = 1.f / red[0];
    v.x *= inv; v.y *= inv; v.z *= inv; v.w *= inv;
    *(float4*)&S[tid * 4] = v;
}

// ---------- T[row,p] = sum_{k: clip(k-q)+128 == p} A[row,k] ----------------
__global__ void __launch_bounds__(256) compute_T()
{
    int row = blockIdx.x;
    int q = row & 1023;
    const float* A = g_S + (size_t)row * LSEQ;
    float* T = g_T + (size_t)row * NPOS;
    __shared__ float sA[1024];
    __shared__ float r0[256], r1[256];
    int tid = threadIdx.x;
    *(float4*)&sA[tid * 4] = *(const float4*)&A[tid * 4];
    __syncthreads();
    if (tid < 255) {                 // middle bins p=1..255 : exactly one k
        int p = tid + 1;
        int k = q + p - 128;
        T[p] = (k >= 0 && k < 1024) ? sA[k] : 0.f;
    }
    float s0 = 0.f;                  // p=0 : k <= q-128
    for (int k = tid; k <= q - 128; k += 256) s0 += sA[k];
    float s1 = 0.f;                  // p=256 : k >= q+128
    for (int k = q + 128 + tid; k < 1024; k += 256) s1 += sA[k];
    r0[tid] = s0; r1[tid] = s1; __syncthreads();
    for (int s = 128; s > 0; s >>= 1) {
        if (tid < s) { r0[tid] += r0[tid + s]; r1[tid] += r1[tid + s]; }
        __syncthreads();
    }
    if (tid == 0) { T[0] = r0[0]; T[256] = r1[0]; }
}

// ---------------- O1 = A @ V, write permuted into g_O ----------------------
__global__ void __launch_bounds__(256) gemm_av()
{
    __shared__ float As[16][64];
    __shared__ float Bs[16][64];
    int z = blockIdx.z;
    const float* A = g_S + (size_t)z * LSEQ * LSEQ;
    const float* V = g_V + (size_t)z * LSEQ * DH;
    int bm = blockIdx.y * 64;          // N = 64 exactly, bn = 0
    int tid = threadIdx.x, tx = tid & 15, ty = tid >> 4;
    float acc[4][4];
#pragma unroll
    for (int i = 0; i < 4; i++)
#pragma unroll
        for (int j = 0; j < 4; j++) acc[i][j] = 0.f;

    int lrow = tid >> 2, lc4 = (tid & 3) * 4;   // A tile 64x16
    int vrow = tid >> 4, vc4 = (tid & 15) * 4;  // V tile 16x64
    for (int k0 = 0; k0 < LSEQ; k0 += 16) {
        float4 av = *(const float4*)&A[(size_t)(bm + lrow) * LSEQ + k0 + lc4];
        As[lc4 + 0][lrow] = av.x; As[lc4 + 1][lrow] = av.y;
        As[lc4 + 2][lrow] = av.z; As[lc4 + 3][lrow] = av.w;
        float4 vv = *(const float4*)&V[(size_t)(k0 + vrow) * 64 + vc4];
        *(float4*)&Bs[vrow][vc4] = vv;
        __syncthreads();
#pragma unroll
        for (int kk = 0; kk < 16; kk++) {
            float a[4], b[4];
            *(float4*)a = *(const float4*)&As[kk][ty * 4];
            *(float4*)b = *(const float4*)&Bs[kk][tx * 4];
#pragma unroll
            for (int i = 0; i < 4; i++)
#pragma unroll
                for (int j = 0; j < 4; j++) acc[i][j] += a[i] * b[j];
        }
        __syncthreads();
    }
    int b = z >> 4, h = z & 15;
#pragma unroll
    for (int i = 0; i < 4; i++) {
        int q = bm + ty * 4 + i;
#pragma unroll
        for (int j = 0; j < 4; j++) {
            int n = tx * 4 + j;
            g_O[((size_t)(b * LSEQ + q)) * DMODEL + h * 64 + n] = acc[i][j];
        }
    }
}

// ---------------- g_O += T @ posV  (M=65536, N=64, K=257) ------------------
__global__ void __launch_bounds__(256) gemm_tposv(const float* __restrict__ posV)
{
    __shared__ float As[16][64];
    __shared__ float Bs[16][64];
    int bm = blockIdx.x * 64;
    int tid = threadIdx.x, tx = tid & 15, ty = tid >> 4;
    float acc[4][4];
#pragma unroll
    for (int i = 0; i < 4; i++)
#pragma unroll
        for (int j = 0; j < 4; j++) acc[i][j] = 0.f;

    int lrow = tid >> 2, lc4 = (tid & 3) * 4;
    int vrow = tid >> 4, vc4 = (tid & 15) * 4;
    for (int k0 = 0; k0 < NPOS; k0 += 16) {
        const float* Trow = g_T + (size_t)(bm + lrow) * NPOS;
#pragma unroll
        for (int i = 0; i < 4; i++) {
            int k = k0 + lc4 + i;
            As[lc4 + i][lrow] = (k < NPOS) ? Trow[k] : 0.f;
        }
        float4 bv = make_float4(0.f, 0.f, 0.f, 0.f);
        if (k0 + vrow < NPOS) bv = *(const float4*)&posV[(size_t)(k0 + vrow) * 64 + vc4];
        *(float4*)&Bs[vrow][vc4] = bv;
        __syncthreads();
#pragma unroll
        for (int kk = 0; kk < 16; kk++) {
            float a[4], b[4];
            *(float4*)a = *(const float4*)&As[kk][ty * 4];
            *(float4*)b = *(const float4*)&Bs[kk][tx * 4];
#pragma unroll
            for (int i = 0; i < 4; i++)
#pragma unroll
                for (int j = 0; j < 4; j++) acc[i][j] += a[i] * b[j];
        }
        __syncthreads();
    }
#pragma unroll
    for (int i = 0; i < 4; i++) {
        int r = bm + ty * 4 + i;
        int z = r >> 10, q = r & 1023;
        int b = z >> 4, h = z & 15;
#pragma unroll
        for (int j = 0; j < 4; j++) {
            size_t idx = ((size_t)(b * LSEQ + q)) * DMODEL + h * 64 + tx * 4 + j;
            g_O[idx] += acc[i][j];
        }
    }
}

// ---------------------------------------------------------------------------
extern "C" void kernel_launch(void* const* d_in, const int* in_sizes, int n_in,
                              void* d_out, int out_size)
{
    const float* x    = (const float*)d_in[0];
    const float* pad  = (const float*)d_in[1];
    const float* Wq   = (const float*)d_in[2];
    const float* bq   = (const float*)d_in[3];
    const float* Wk   = (const float*)d_in[4];
    const float* bk   = (const float*)d_in[5];
    const float* Wv   = (const float*)d_in[6];
    const float* bv   = (const float*)d_in[7];
    const float* Wo   = (const float*)d_in[8];
    const float* bo   = (const float*)d_in[9];
    const float* posK = (const float*)d_in[10];
    const float* posV = (const float*)d_in[11];
    float* out = (float*)d_out;

    float *Qp, *Kp, *Vp, *Op;
    cudaGetSymbolAddress((void**)&Qp, g_Q);
    cudaGetSymbolAddress((void**)&Kp, g_K);
    cudaGetSymbolAddress((void**)&Vp, g_V);
    cudaGetSymbolAddress((void**)&Op, g_O);

    dim3 g128(DMODEL / 128, MROW / 128);   // (8, 32)
    gemm_proj<true><<<g128, 256>>>(x, Wq, bq, Qp, MROW, DMODEL, DMODEL);
    gemm_proj<true><<<g128, 256>>>(x, Wk, bk, Kp, MROW, DMODEL, DMODEL);
    gemm_proj<true><<<g128, 256>>>(x, Wv, bv, Vp, MROW, DMODEL, DMODEL);

    gemm_qposk<<<dim3((NPOS + 63) / 64, ROWS / 64), 256>>>(posK);
    attn_scores<<<dim3(16, 16, BH), 256>>>(pad);
    softmax_k<<<ROWS, 256>>>();
    compute_T<<<ROWS, 256>>>();
    gemm_av<<<dim3(1, 16, BH), 256>>>();
    gemm_tposv<<<dim3(ROWS / 64), 256>>>(posV);

    gemm_proj<false><<<g128, 256>>>(Op, Wo, bo, out, MROW, DMODEL, DMODEL);
}

// round 2
// speedup vs baseline: 1.9095x; 1.9095x over previous
#include <cuda_runtime.h>
#include <cstdint>

#define NH     16
#define DH     64
#define LSEQ   1024
#define NB     4
#define DMODEL 1024
#define NPOS   257
#define BH     (NB*NH)       // 64
#define ROWS   (BH*LSEQ)     // 65536
#define MROW   (NB*LSEQ)     // 4096

// ---------------- scratch (device globals; no allocation allowed) ----------
__device__ float g_Q[(size_t)ROWS*DH];        // [B,H,L,d]
__device__ float g_K[(size_t)ROWS*DH];
__device__ float g_V[(size_t)ROWS*DH];
__device__ float g_R[(size_t)ROWS*NPOS];      // Q . posK^T
__device__ float g_T[(size_t)ROWS*NPOS];      // scattered A
__device__ float g_S[(size_t)ROWS*LSEQ];      // scores / attn probs (268MB)
__device__ float g_O[(size_t)MROW*DMODEL];    // (O1+O2) in [B,L,D] layout

// ---------------- tf32 mma helpers -----------------------------------------
__device__ __forceinline__ unsigned f2tf(float f) {
    unsigned u;
    asm("cvt.rna.tf32.f32 %0, %1;" : "=r"(u) : "f"(f));
    return u;
}

__device__ __forceinline__ void mma_tf32(float* d, const unsigned* a, const unsigned* b) {
    asm volatile(
        "mma.sync.aligned.m16n8k8.row.col.f32.tf32.tf32.f32 "
        "{%0,%1,%2,%3}, {%4,%5,%6,%7}, {%8,%9}, {%0,%1,%2,%3};\n"
        : "+f"(d[0]), "+f"(d[1]), "+f"(d[2]), "+f"(d[3])
        : "r"(a[0]), "r"(a[1]), "r"(a[2]), "r"(a[3]), "r"(b[0]), "r"(b[1]));
}

// ============ tf32 tensor-core GEMM: C = A@W + bias (128x128 tiles) =========
// HEADMAJOR: write C at [((b*H+h)*L + l)*64 + dd] instead of row-major.
template<bool HEADMAJOR>
__global__ void __launch_bounds__(256) gemm_proj_t(
    const float* __restrict__ A, const float* __restrict__ W,
    const float* __restrict__ bias, float* __restrict__ C,
    int K, int N)
{
    __shared__ __align__(16) unsigned As[128][36];   // [m][k] pad->stride 36
    __shared__ __align__(16) unsigned Bs[32][136];   // [k][n] pad->stride 136
    int tid = threadIdx.x;
    int bm = blockIdx.y * 128, bn = blockIdx.x * 128;
    int warp = tid >> 5, lane = tid & 31;
    int wm = (warp >> 2) * 64, wn = (warp & 3) * 32;
    int g = lane >> 2, i4 = lane & 3;

    float acc[4][4][4] = {};

    int am = tid >> 3, ak = (tid & 7) * 4;
    int bk = tid >> 5, bn4 = (tid & 31) * 4;

    for (int k0 = 0; k0 < K; k0 += 32) {
#pragma unroll
        for (int r = 0; r < 4; r++) {
            float4 v = *(const float4*)&A[(size_t)(bm + am + 32 * r) * K + k0 + ak];
            uint4 u = make_uint4(f2tf(v.x), f2tf(v.y), f2tf(v.z), f2tf(v.w));
            *(uint4*)&As[am + 32 * r][ak] = u;
            float4 w = *(const float4*)&W[(size_t)(k0 + bk + 8 * r) * N + bn + bn4];
            uint4 uw = make_uint4(f2tf(w.x), f2tf(w.y), f2tf(w.z), f2tf(w.w));
            *(uint4*)&Bs[bk + 8 * r][bn4] = uw;
        }
        __syncthreads();
#pragma unroll
        for (int ks = 0; ks < 32; ks += 8) {
            unsigned af[4][4], bf[4][2];
#pragma unroll
            for (int mi = 0; mi < 4; mi++) {
                int r0 = wm + 16 * mi + g;
                af[mi][0] = As[r0][ks + i4];
                af[mi][1] = As[r0 + 8][ks + i4];
                af[mi][2] = As[r0][ks + i4 + 4];
                af[mi][3] = As[r0 + 8][ks + i4 + 4];
            }
#pragma unroll
            for (int ni = 0; ni < 4; ni++) {
                bf[ni][0] = Bs[ks + i4][wn + 8 * ni + g];
                bf[ni][1] = Bs[ks + i4 + 4][wn + 8 * ni + g];
            }
#pragma unroll
            for (int mi = 0; mi < 4; mi++)
#pragma unroll
                for (int ni = 0; ni < 4; ni++)
                    mma_tf32(acc[mi][ni], af[mi], bf[ni]);
        }
        __syncthreads();
    }

#pragma unroll
    for (int mi = 0; mi < 4; mi++) {
#pragma unroll
        for (int ni = 0; ni < 4; ni++) {
#pragma unroll
            for (int e = 0; e < 4; e++) {
                int r = bm + wm + 16 * mi + g + (e >> 1) * 8;
                int c = bn + wn + 8 * ni + 2 * i4 + (e & 1);
                float v = acc[mi][ni][e] + bias[c];
                if (HEADMAJOR) {
                    int b = r >> 10, l = r & 1023, h = c >> 6, dd = c & 63;
                    C[(((size_t)(b * NH + h) * LSEQ + l) << 6) + dd] = v;
                } else {
                    C[(size_t)r * N + c] = v;
                }
            }
        }
    }
}

// ===== S = (Q K^T + gather(R)) * 0.125 * pad, tf32 mma, batched over bh =====
__global__ void __launch_bounds__(256) attn_scores_t(const float* __restrict__ pad)
{
    __shared__ __align__(16) unsigned Qs[128][36];
    __shared__ __align__(16) unsigned Ks[128][36];
    int z = blockIdx.z;
    const float* Qp = g_Q + (size_t)z * LSEQ * DH;
    const float* Kp = g_K + (size_t)z * LSEQ * DH;
    int bm = blockIdx.y * 128, bn = blockIdx.x * 128;
    int tid = threadIdx.x;
    int warp = tid >> 5, lane = tid & 31;
    int wm = (warp >> 2) * 64, wn = (warp & 3) * 32;
    int g = lane >> 2, i4 = lane & 3;

    float acc[4][4][4] = {};
    int am = tid >> 3, ak = (tid & 7) * 4;

    for (int k0 = 0; k0 < DH; k0 += 32) {
#pragma unroll
        for (int r = 0; r < 4; r++) {
            float4 v = *(const float4*)&Qp[(size_t)(bm + am + 32 * r) * DH + k0 + ak];
            *(uint4*)&Qs[am + 32 * r][ak] =
                make_uint4(f2tf(v.x), f2tf(v.y), f2tf(v.z), f2tf(v.w));
            float4 w = *(const float4*)&Kp[(size_t)(bn + am + 32 * r) * DH + k0 + ak];
            *(uint4*)&Ks[am + 32 * r][ak] =
                make_uint4(f2tf(w.x), f2tf(w.y), f2tf(w.z), f2tf(w.w));
        }
        __syncthreads();
#pragma unroll
        for (int ks = 0; ks < 32; ks += 8) {
            unsigned af[4][4], bf[4][2];
#pragma unroll
            for (int mi = 0; mi < 4; mi++) {
                int r0 = wm + 16 * mi + g;
                af[mi][0] = Qs[r0][ks + i4];
                af[mi][1] = Qs[r0 + 8][ks + i4];
                af[mi][2] = Qs[r0][ks + i4 + 4];
                af[mi][3] = Qs[r0 + 8][ks + i4 + 4];
            }
#pragma unroll
            for (int ni = 0; ni < 4; ni++) {
                int n0 = wn + 8 * ni + g;
                bf[ni][0] = Ks[n0][ks + i4];
                bf[ni][1] = Ks[n0][ks + i4 + 4];
            }
#pragma unroll
            for (int mi = 0; mi < 4; mi++)
#pragma unroll
                for (int ni = 0; ni < 4; ni++)
                    mma_tf32(acc[mi][ni], af[mi], bf[ni]);
        }
        __syncthreads();
    }

    int b = z >> 4;
#pragma unroll
    for (int mi = 0; mi < 4; mi++) {
#pragma unroll
        for (int ni = 0; ni < 4; ni++) {
#pragma unroll
            for (int e = 0; e < 4; e++) {
                int q = bm + wm + 16 * mi + g + (e >> 1) * 8;
                int kp = bn + wn + 8 * ni + 2 * i4 + (e & 1);
                int dlt = min(max(kp - q, -128), 128);
                float r2 = g_R[((size_t)z * LSEQ + q) * NPOS + dlt + 128];
                g_S[((size_t)z * LSEQ + q) * LSEQ + kp] =
                    (acc[mi][ni][e] + r2) * 0.125f * pad[b * LSEQ + kp];
            }
        }
    }
}

// =========== O1 = A @ V (tf32 mma), write permuted into g_O =================
__global__ void __launch_bounds__(256) gemm_av_t()
{
    __shared__ __align__(16) unsigned As[128][36];
    __shared__ __align__(16) unsigned Bs[32][72];
    int z = blockIdx.y;
    const float* A = g_S + (size_t)z * LSEQ * LSEQ;
    const float* V = g_V + (size_t)z * LSEQ * DH;
    int bm = blockIdx.x * 128;
    int tid = threadIdx.x;
    int warp = tid >> 5, lane = tid & 31;
    int wm = (warp >> 1) * 32, wn = (warp & 1) * 32;
    int g = lane >> 2, i4 = lane & 3;

    float acc[2][4][4] = {};
    int am = tid >> 3, ak = (tid & 7) * 4;
    int vk = tid >> 4, vn4 = (tid & 15) * 4;

    for (int k0 = 0; k0 < LSEQ; k0 += 32) {
#pragma unroll
        for (int r = 0; r < 4; r++) {
            float4 v = *(const float4*)&A[(size_t)(bm + am + 32 * r) * LSEQ + k0 + ak];
            *(uint4*)&As[am + 32 * r][ak] =
                make_uint4(f2tf(v.x), f2tf(v.y), f2tf(v.z), f2tf(v.w));
        }
#pragma unroll
        for (int r = 0; r < 2; r++) {
            float4 w = *(const float4*)&V[(size_t)(k0 + vk + 16 * r) * DH + vn4];
            *(uint4*)&Bs[vk + 16 * r][vn4] =
                make_uint4(f2tf(w.x), f2tf(w.y), f2tf(w.z), f2tf(w.w));
        }
        __syncthreads();
#pragma unroll
        for (int ks = 0; ks < 32; ks += 8) {
            unsigned af[2][4], bf[4][2];
#pragma unroll
            for (int mi = 0; mi < 2; mi++) {
                int r0 = wm + 16 * mi + g;
                af[mi][0] = As[r0][ks + i4];
                af[mi][1] = As[r0 + 8][ks + i4];
                af[mi][2] = As[r0][ks + i4 + 4];
                af[mi][3] = As[r0 + 8][ks + i4 + 4];
            }
#pragma unroll
            for (int ni = 0; ni < 4; ni++) {
                bf[ni][0] = Bs[ks + i4][wn + 8 * ni + g];
                bf[ni][1] = Bs[ks + i4 + 4][wn + 8 * ni + g];
            }
#pragma unroll
            for (int mi = 0; mi < 2; mi++)
#pragma unroll
                for (int ni = 0; ni < 4; ni++)
                    mma_tf32(acc[mi][ni], af[mi], bf[ni]);
        }
        __syncthreads();
    }

    int b = z >> 4, h = z & 15;
#pragma unroll
    for (int mi = 0; mi < 2; mi++) {
#pragma unroll
        for (int ni = 0; ni < 4; ni++) {
#pragma unroll
            for (int e = 0; e < 4; e++) {
                int q = bm + wm + 16 * mi + g + (e >> 1) * 8;
                int n = wn + 8 * ni + 2 * i4 + (e & 1);
                g_O[((size_t)(b * LSEQ + q)) * DMODEL + h * 64 + n] = acc[mi][ni][e];
            }
        }
    }
}

// ---------------- R = Q @ posK^T  (M=65536, N=257, K=64) -------------------
__global__ void __launch_bounds__(256) gemm_qposk(const float* __restrict__ posK)
{
    __shared__ float As[16][64];
    __shared__ float Bs[16][64];
    int tid = threadIdx.x, tx = tid & 15, ty = tid >> 4;
    int bm = blockIdx.y * 64, bn = blockIdx.x * 64;
    float acc[4][4];
#pragma unroll
    for (int i = 0; i < 4; i++)
#pragma unroll
        for (int j = 0; j < 4; j++) acc[i][j] = 0.f;

    int lrow = tid >> 2, lc4 = (tid & 3) * 4;
    for (int k0 = 0; k0 < 64; k0 += 16) {
        float4 av = *(const float4*)&g_Q[(size_t)(bm + lrow) * 64 + k0 + lc4];
        As[lc4 + 0][lrow] = av.x; As[lc4 + 1][lrow] = av.y;
        As[lc4 + 2][lrow] = av.z; As[lc4 + 3][lrow] = av.w;
        int n = bn + lrow;
        float4 bv = make_float4(0.f, 0.f, 0.f, 0.f);
        if (n < NPOS) bv = *(const float4*)&posK[(size_t)n * 64 + k0 + lc4];
        Bs[lc4 + 0][lrow] = bv.x; Bs[lc4 + 1][lrow] = bv.y;
        Bs[lc4 + 2][lrow] = bv.z; Bs[lc4 + 3][lrow] = bv.w;
        __syncthreads();
#pragma unroll
        for (int kk = 0; kk < 16; kk++) {
            float a[4], b[4];
            *(float4*)a = *(const float4*)&As[kk][ty * 4];
            *(float4*)b = *(const float4*)&Bs[kk][tx * 4];
#pragma unroll
            for (int i = 0; i < 4; i++)
#pragma unroll
                for (int j = 0; j < 4; j++) acc[i][j] += a[i] * b[j];
        }
        __syncthreads();
    }
#pragma unroll
    for (int i = 0; i < 4; i++) {
        int r = bm + ty * 4 + i;
#pragma unroll
        for (int j = 0; j < 4; j++) {
            int n = bn + tx * 4 + j;
            if (n < NPOS) g_R[(size_t)r * NPOS + n] = acc[i][j];
        }
    }
}

// ---------------- softmax over last axis, in-place -------------------------
__global__ void __launch_bounds__(256) softmax_k()
{
    int row = blockIdx.x;
    float* S = g_S + (size_t)row * LSEQ;
    int tid = threadIdx.x;
    __shared__ float red[256];
    float4 v = *(float4*)&S[tid * 4];
    float m = fmaxf(fmaxf(v.x, v.y), fmaxf(v.z, v.w));
    red[tid] = m; __syncthreads();
    for (int s = 128; s > 0; s >>= 1) {
        if (tid < s) red[tid] = fmaxf(red[tid], red[tid + s]);
        __syncthreads();
    }
    m = red[0]; __syncthreads();
    v.x = __expf(v.x - m); v.y = __expf(v.y - m);
    v.z = __expf(v.z - m); v.w = __expf(v.w - m);
    red[tid] = v.x + v.y + v.z + v.w; __syncthreads();
    for (int s = 128; s > 0; s >>= 1) {
        if (tid < s) red[tid] += red[tid + s];
        __syncthreads();
    }
    float inv = 1.f / red[0];
    v.x *= inv; v.y *= inv; v.z *= inv; v.w *= inv;
    *(float4*)&S[tid * 4] = v;
}

// ---------- T[row,p] = sum_{k: clip(k-q)+128 == p} A[row,k] ----------------
__global__ void __launch_bounds__(256) compute_T()
{
    int row = blockIdx.x;
    int q = row & 1023;
    const float* A = g_S + (size_t)row * LSEQ;
    float* T = g_T + (size_t)row * NPOS;
    __shared__ float sA[1024];
    __shared__ float r0[256], r1[256];
    int tid = threadIdx.x;
    *(float4*)&sA[tid * 4] = *(const float4*)&A[tid * 4];
    __syncthreads();
    if (tid < 255) {                 // middle bins p=1..255 : exactly one k
        int p = tid + 1;
        int k = q + p - 128;
        T[p] = (k >= 0 && k < 1024) ? sA[k] : 0.f;
    }
    float s0 = 0.f;                  // p=0 : k <= q-128
    for (int k = tid; k <= q - 128; k += 256) s0 += sA[k];
    float s1 = 0.f;                  // p=256 : k >= q+128
    for (int k = q + 128 + tid; k < 1024; k += 256) s1 += sA[k];
    r0[tid] = s0; r1[tid] = s1; __syncthreads();
    for (int s = 128; s > 0; s >>= 1) {
        if (tid < s) { r0[tid] += r0[tid + s]; r1[tid] += r1[tid + s]; }
        __syncthreads();
    }
    if (tid == 0) { T[0] = r0[0]; T[256] = r1[0]; }
}

// ---------------- g_O += T @ posV  (M=65536, N=64, K=257) ------------------
__global__ void __launch_bounds__(256) gemm_tposv(const float* __restrict__ posV)
{
    __shared__ float As[16][64];
    __shared__ float Bs[16][64];
    int bm = blockIdx.x * 64;
    int tid = threadIdx.x, tx = tid & 15, ty = tid >> 4;
    float acc[4][4];
#pragma unroll
    for (int i = 0; i < 4; i++)
#pragma unroll
        for (int j = 0; j < 4; j++) acc[i][j] = 0.f;

    int lrow = tid >> 2, lc4 = (tid & 3) * 4;
    int vrow = tid >> 4, vc4 = (tid & 15) * 4;
    for (int k0 = 0; k0 < NPOS; k0 += 16) {
        const float* Trow = g_T + (size_t)(bm + lrow) * NPOS;
#pragma unroll
        for (int i = 0; i < 4; i++) {
            int k = k0 + lc4 + i;
            As[lc4 + i][lrow] = (k < NPOS) ? Trow[k] : 0.f;
        }
        float4 bv = make_float4(0.f, 0.f, 0.f, 0.f);
        if (k0 + vrow < NPOS) bv = *(const float4*)&posV[(size_t)(k0 + vrow) * 64 + vc4];
        *(float4*)&Bs[vrow][vc4] = bv;
        __syncthreads();
#pragma unroll
        for (int kk = 0; kk < 16; kk++) {
            float a[4], b[4];
            *(float4*)a = *(const float4*)&As[kk][ty * 4];
            *(float4*)b = *(const float4*)&Bs[kk][tx * 4];
#pragma unroll
            for (int i = 0; i < 4; i++)
#pragma unroll
                for (int j = 0; j < 4; j++) acc[i][j] += a[i] * b[j];
        }
        __syncthreads();
    }
#pragma unroll
    for (int i = 0; i < 4; i++) {
        int r = bm + ty * 4 + i;
        int z = r >> 10, q = r & 1023;
        int b = z >> 4, h = z & 15;
#pragma unroll
        for (int j = 0; j < 4; j++) {
            size_t idx = ((size_t)(b * LSEQ + q)) * DMODEL + h * 64 + tx * 4 + j;
            g_O[idx] += acc[i][j];
        }
    }
}

// ---------------------------------------------------------------------------
extern "C" void kernel_launch(void* const* d_in, const int* in_sizes, int n_in,
                              void* d_out, int out_size)
{
    const float* x    = (const float*)d_in[0];
    const float* pad  = (const float*)d_in[1];
    const float* Wq   = (const float*)d_in[2];
    const float* bq   = (const float*)d_in[3];
    const float* Wk   = (const float*)d_in[4];
    const float* bk   = (const float*)d_in[5];
    const float* Wv   = (const float*)d_in[6];
    const float* bv   = (const float*)d_in[7];
    const float* Wo   = (const float*)d_in[8];
    const float* bo   = (const float*)d_in[9];
    const float* posK = (const float*)d_in[10];
    const float* posV = (const float*)d_in[11];
    float* out = (float*)d_out;

    float *Qp, *Kp, *Vp, *Op;
    cudaGetSymbolAddress((void**)&Qp, g_Q);
    cudaGetSymbolAddress((void**)&Kp, g_K);
    cudaGetSymbolAddress((void**)&Vp, g_V);
    cudaGetSymbolAddress((void**)&Op, g_O);

    dim3 g128(DMODEL / 128, MROW / 128);   // (8, 32)
    gemm_proj_t<true><<<g128, 256>>>(x, Wq, bq, Qp, DMODEL, DMODEL);
    gemm_proj_t<true><<<g128, 256>>>(x, Wk, bk, Kp, DMODEL, DMODEL);
    gemm_proj_t<true><<<g128, 256>>>(x, Wv, bv, Vp, DMODEL, DMODEL);

    gemm_qposk<<<dim3((NPOS + 63) / 64, ROWS / 64), 256>>>(posK);
    attn_scores_t<<<dim3(8, 8, BH), 256>>>(pad);
    softmax_k<<<ROWS, 256>>>();
    compute_T<<<ROWS, 256>>>();
    gemm_av_t<<<dim3(8, BH), 256>>>();
    gemm_tposv<<<dim3(ROWS / 64), 256>>>(posV);

    gemm_proj_t<false><<<g128, 256>>>(Op, Wo, bo, out, DMODEL, DMODEL);
}

// round 3
// speedup vs baseline: 2.0942x; 1.0967x over previous
#include <cuda_runtime.h>
#include <cstdint>

#define NH     16
#define DH     64
#define LSEQ   1024
#define NB     4
#define DMODEL 1024
#define NPOS   257
#define TP     288           // padded stride for T (9 k-chunks of 32)
#define BH     (NB*NH)       // 64
#define ROWS   (BH*LSEQ)     // 65536
#define MROW   (NB*LSEQ)     // 4096

// ---------------- scratch (device globals; no allocation allowed) ----------
__device__ float g_Q[(size_t)ROWS*DH];        // [B,H,L,d]
__device__ float g_K[(size_t)ROWS*DH];
__device__ float g_V[(size_t)ROWS*DH];
__device__ float g_R[(size_t)ROWS*NPOS];      // Q . posK^T
__device__ float g_T[(size_t)ROWS*TP];        // scattered A (padded stride)
__device__ float g_S[(size_t)ROWS*LSEQ];      // scores / attn probs (268MB)
__device__ float g_O[(size_t)MROW*DMODEL];    // (O1+O2) in [B,L,D] layout

// ---------------- tf32 mma helpers -----------------------------------------
__device__ __forceinline__ unsigned f2tf(float f) {
    unsigned u;
    asm("cvt.rna.tf32.f32 %0, %1;" : "=r"(u) : "f"(f));
    return u;
}

__device__ __forceinline__ void mma_tf32(float* d, const unsigned* a, const unsigned* b) {
    asm volatile(
        "mma.sync.aligned.m16n8k8.row.col.f32.tf32.tf32.f32 "
        "{%0,%1,%2,%3}, {%4,%5,%6,%7}, {%8,%9}, {%0,%1,%2,%3};\n"
        : "+f"(d[0]), "+f"(d[1]), "+f"(d[2]), "+f"(d[3])
        : "r"(a[0]), "r"(a[1]), "r"(a[2]), "r"(a[3]), "r"(b[0]), "r"(b[1]));
}

// ============ tf32 tensor-core GEMM: C = A@W + bias (128x128 tiles) =========
// Register-prefetch pipelined: next tile's LDGs issued before compute phase.
template<bool HEADMAJOR>
__global__ void __launch_bounds__(256) gemm_proj_t(
    const float* __restrict__ A, const float* __restrict__ W,
    const float* __restrict__ bias, float* __restrict__ C,
    int K, int N)
{
    __shared__ __align__(16) unsigned As[128][36];   // [m][k]
    __shared__ __align__(16) unsigned Bs[32][136];   // [k][n]
    int tid = threadIdx.x;
    int bm = blockIdx.y * 128, bn = blockIdx.x * 128;
    int warp = tid >> 5, lane = tid & 31;
    int wm = (warp >> 2) * 64, wn = (warp & 3) * 32;
    int g = lane >> 2, i4 = lane & 3;

    float acc[4][4][4] = {};

    int am = tid >> 3, ak = (tid & 7) * 4;
    int bk = tid >> 5, bn4 = (tid & 31) * 4;

    float4 ra[4], rw[4];
#pragma unroll
    for (int r = 0; r < 4; r++) {
        ra[r] = *(const float4*)&A[(size_t)(bm + am + 32 * r) * K + ak];
        rw[r] = *(const float4*)&W[(size_t)(bk + 8 * r) * N + bn + bn4];
    }

    for (int k0 = 0; k0 < K; k0 += 32) {
#pragma unroll
        for (int r = 0; r < 4; r++) {
            *(uint4*)&As[am + 32 * r][ak] =
                make_uint4(f2tf(ra[r].x), f2tf(ra[r].y), f2tf(ra[r].z), f2tf(ra[r].w));
            *(uint4*)&Bs[bk + 8 * r][bn4] =
                make_uint4(f2tf(rw[r].x), f2tf(rw[r].y), f2tf(rw[r].z), f2tf(rw[r].w));
        }
        __syncthreads();
        if (k0 + 32 < K) {
#pragma unroll
            for (int r = 0; r < 4; r++) {
                ra[r] = *(const float4*)&A[(size_t)(bm + am + 32 * r) * K + k0 + 32 + ak];
                rw[r] = *(const float4*)&W[(size_t)(k0 + 32 + bk + 8 * r) * N + bn + bn4];
            }
        }
#pragma unroll
        for (int ks = 0; ks < 32; ks += 8) {
            unsigned af[4][4], bf[4][2];
#pragma unroll
            for (int mi = 0; mi < 4; mi++) {
                int r0 = wm + 16 * mi + g;
                af[mi][0] = As[r0][ks + i4];
                af[mi][1] = As[r0 + 8][ks + i4];
                af[mi][2] = As[r0][ks + i4 + 4];
                af[mi][3] = As[r0 + 8][ks + i4 + 4];
            }
#pragma unroll
            for (int ni = 0; ni < 4; ni++) {
                bf[ni][0] = Bs[ks + i4][wn + 8 * ni + g];
                bf[ni][1] = Bs[ks + i4 + 4][wn + 8 * ni + g];
            }
#pragma unroll
            for (int mi = 0; mi < 4; mi++)
#pragma unroll
                for (int ni = 0; ni < 4; ni++)
                    mma_tf32(acc[mi][ni], af[mi], bf[ni]);
        }
        __syncthreads();
    }

#pragma unroll
    for (int mi = 0; mi < 4; mi++) {
#pragma unroll
        for (int ni = 0; ni < 4; ni++) {
#pragma unroll
            for (int e = 0; e < 4; e++) {
                int r = bm + wm + 16 * mi + g + (e >> 1) * 8;
                int c = bn + wn + 8 * ni + 2 * i4 + (e & 1);
                float v = acc[mi][ni][e] + bias[c];
                if (HEADMAJOR) {
                    int b = r >> 10, l = r & 1023, h = c >> 6, dd = c & 63;
                    C[(((size_t)(b * NH + h) * LSEQ + l) << 6) + dd] = v;
                } else {
                    C[(size_t)r * N + c] = v;
                }
            }
        }
    }
}

// ======== R = Q @ posK^T (tf32 mma; M=65536, N=257->3x128, K=64) ===========
__global__ void __launch_bounds__(256) gemm_qposk_t(const float* __restrict__ posK)
{
    __shared__ __align__(16) unsigned As[128][36];
    __shared__ __align__(16) unsigned Bs[32][132];
    int tid = threadIdx.x;
    int bm = blockIdx.y * 128, bn = blockIdx.x * 128;
    int warp = tid >> 5, lane = tid & 31;
    int wm = (warp >> 2) * 64, wn = (warp & 3) * 32;
    int g = lane >> 2, i4 = lane & 3;

    float acc[4][4][4] = {};
    int am = tid >> 3, ak = (tid & 7) * 4;
    int nl = tid >> 3, k4 = (tid & 7) * 4;

    for (int k0 = 0; k0 < DH; k0 += 32) {
#pragma unroll
        for (int r = 0; r < 4; r++) {
            float4 v = *(const float4*)&g_Q[(size_t)(bm + am + 32 * r) * DH + k0 + ak];
            *(uint4*)&As[am + 32 * r][ak] =
                make_uint4(f2tf(v.x), f2tf(v.y), f2tf(v.z), f2tf(v.w));
            int n = bn + nl + 32 * r;
            float4 w = make_float4(0.f, 0.f, 0.f, 0.f);
            if (n < NPOS) w = *(const float4*)&posK[(size_t)n * DH + k0 + k4];
            Bs[k4 + 0][nl + 32 * r] = f2tf(w.x);
            Bs[k4 + 1][nl + 32 * r] = f2tf(w.y);
            Bs[k4 + 2][nl + 32 * r] = f2tf(w.z);
            Bs[k4 + 3][nl + 32 * r] = f2tf(w.w);
        }
        __syncthreads();
#pragma unroll
        for (int ks = 0; ks < 32; ks += 8) {
            unsigned af[4][4], bf[4][2];
#pragma unroll
            for (int mi = 0; mi < 4; mi++) {
                int r0 = wm + 16 * mi + g;
                af[mi][0] = As[r0][ks + i4];
                af[mi][1] = As[r0 + 8][ks + i4];
                af[mi][2] = As[r0][ks + i4 + 4];
                af[mi][3] = As[r0 + 8][ks + i4 + 4];
            }
#pragma unroll
            for (int ni = 0; ni < 4; ni++) {
                bf[ni][0] = Bs[ks + i4][wn + 8 * ni + g];
                bf[ni][1] = Bs[ks + i4 + 4][wn + 8 * ni + g];
            }
#pragma unroll
            for (int mi = 0; mi < 4; mi++)
#pragma unroll
                for (int ni = 0; ni < 4; ni++)
                    mma_tf32(acc[mi][ni], af[mi], bf[ni]);
        }
        __syncthreads();
    }

#pragma unroll
    for (int mi = 0; mi < 4; mi++) {
#pragma unroll
        for (int ni = 0; ni < 4; ni++) {
#pragma unroll
            for (int e = 0; e < 4; e++) {
                int r = bm + wm + 16 * mi + g + (e >> 1) * 8;
                int n = bn + wn + 8 * ni + 2 * i4 + (e & 1);
                if (n < NPOS) g_R[(size_t)r * NPOS + n] = acc[mi][ni][e];
            }
        }
    }
}

// ===== S = (Q K^T + gather(R)) * 0.125 * pad, tf32 mma, batched over bh =====
__global__ void __launch_bounds__(256) attn_scores_t(const float* __restrict__ pad)
{
    __shared__ __align__(16) unsigned Qs[128][36];
    __shared__ __align__(16) unsigned Ks[128][36];
    int z = blockIdx.z;
    const float* Qp = g_Q + (size_t)z * LSEQ * DH;
    const float* Kp = g_K + (size_t)z * LSEQ * DH;
    int bm = blockIdx.y * 128, bn = blockIdx.x * 128;
    int tid = threadIdx.x;
    int warp = tid >> 5, lane = tid & 31;
    int wm = (warp >> 2) * 64, wn = (warp & 3) * 32;
    int g = lane >> 2, i4 = lane & 3;

    float acc[4][4][4] = {};
    int am = tid >> 3, ak = (tid & 7) * 4;

    for (int k0 = 0; k0 < DH; k0 += 32) {
#pragma unroll
        for (int r = 0; r < 4; r++) {
            float4 v = *(const float4*)&Qp[(size_t)(bm + am + 32 * r) * DH + k0 + ak];
            *(uint4*)&Qs[am + 32 * r][ak] =
                make_uint4(f2tf(v.x), f2tf(v.y), f2tf(v.z), f2tf(v.w));
            float4 w = *(const float4*)&Kp[(size_t)(bn + am + 32 * r) * DH + k0 + ak];
            *(uint4*)&Ks[am + 32 * r][ak] =
                make_uint4(f2tf(w.x), f2tf(w.y), f2tf(w.z), f2tf(w.w));
        }
        __syncthreads();
#pragma unroll
        for (int ks = 0; ks < 32; ks += 8) {
            unsigned af[4][4], bf[4][2];
#pragma unroll
            for (int mi = 0; mi < 4; mi++) {
                int r0 = wm + 16 * mi + g;
                af[mi][0] = Qs[r0][ks + i4];
                af[mi][1] = Qs[r0 + 8][ks + i4];
                af[mi][2] = Qs[r0][ks + i4 + 4];
                af[mi][3] = Qs[r0 + 8][ks + i4 + 4];
            }
#pragma unroll
            for (int ni = 0; ni < 4; ni++) {
                int n0 = wn + 8 * ni + g;
                bf[ni][0] = Ks[n0][ks + i4];
                bf[ni][1] = Ks[n0][ks + i4 + 4];
            }
#pragma unroll
            for (int mi = 0; mi < 4; mi++)
#pragma unroll
                for (int ni = 0; ni < 4; ni++)
                    mma_tf32(acc[mi][ni], af[mi], bf[ni]);
        }
        __syncthreads();
    }

    int b = z >> 4;
#pragma unroll
    for (int mi = 0; mi < 4; mi++) {
#pragma unroll
        for (int ni = 0; ni < 4; ni++) {
#pragma unroll
            for (int e = 0; e < 4; e++) {
                int q = bm + wm + 16 * mi + g + (e >> 1) * 8;
                int kp = bn + wn + 8 * ni + 2 * i4 + (e & 1);
                int dlt = min(max(kp - q, -128), 128);
                float r2 = g_R[((size_t)z * LSEQ + q) * NPOS + dlt + 128];
                g_S[((size_t)z * LSEQ + q) * LSEQ + kp] =
                    (acc[mi][ni][e] + r2) * 0.125f * pad[b * LSEQ + kp];
            }
        }
    }
}

// ====== fused softmax (in-place on g_S) + T scatter (padded stride) ========
__global__ void __launch_bounds__(256) softmax_T()
{
    int row = blockIdx.x;
    int q = row & 1023;
    float* S = g_S + (size_t)row * LSEQ;
    float* T = g_T + (size_t)row * TP;
    int tid = threadIdx.x;
    __shared__ float sA[1024];
    __shared__ float red[256];
    __shared__ float r0s[256], r1s[256];

    float4 v = *(float4*)&S[tid * 4];
    float m = fmaxf(fmaxf(v.x, v.y), fmaxf(v.z, v.w));
    red[tid] = m; __syncthreads();
    for (int s = 128; s > 0; s >>= 1) {
        if (tid < s) red[tid] = fmaxf(red[tid], red[tid + s]);
        __syncthreads();
    }
    m = red[0]; __syncthreads();
    v.x = __expf(v.x - m); v.y = __expf(v.y - m);
    v.z = __expf(v.z - m); v.w = __expf(v.w - m);
    red[tid] = v.x + v.y + v.z + v.w; __syncthreads();
    for (int s = 128; s > 0; s >>= 1) {
        if (tid < s) red[tid] += red[tid + s];
        __syncthreads();
    }
    float inv = 1.f / red[0];
    v.x *= inv; v.y *= inv; v.z *= inv; v.w *= inv;
    *(float4*)&S[tid * 4] = v;
    *(float4*)&sA[tid * 4] = v;
    __syncthreads();

    if (tid < 255) {                 // middle bins p=1..255 : exactly one k
        int p = tid + 1;
        int k = q + p - 128;
        T[p] = (k >= 0 && k < 1024) ? sA[k] : 0.f;
    }
    if (tid == 255) {                // zero tail 257..287 handled below
    }
    float s0 = 0.f;                  // p=0 : k <= q-128
    for (int k = tid; k <= q - 128; k += 256) s0 += sA[k];
    float s1 = 0.f;                  // p=256 : k >= q+128
    for (int k = q + 128 + tid; k < 1024; k += 256) s1 += sA[k];
    r0s[tid] = s0; r1s[tid] = s1; __syncthreads();
    for (int s = 128; s > 0; s >>= 1) {
        if (tid < s) { r0s[tid] += r0s[tid + s]; r1s[tid] += r1s[tid + s]; }
        __syncthreads();
    }
    if (tid == 0) { T[0] = r0s[0]; T[256] = r1s[0]; }
    if (tid < TP - NPOS) T[NPOS + tid] = 0.f;   // zero pad 257..287
}

// =========== O1 = A @ V (tf32 mma, prefetched), write permuted =============
__global__ void __launch_bounds__(256) gemm_av_t()
{
    __shared__ __align__(16) unsigned As[128][36];
    __shared__ __align__(16) unsigned Bs[32][72];
    int z = blockIdx.y;
    const float* A = g_S + (size_t)z * LSEQ * LSEQ;
    const float* V = g_V + (size_t)z * LSEQ * DH;
    int bm = blockIdx.x * 128;
    int tid = threadIdx.x;
    int warp = tid >> 5, lane = tid & 31;
    int wm = (warp >> 1) * 32, wn = (warp & 1) * 32;
    int g = lane >> 2, i4 = lane & 3;

    float acc[2][4][4] = {};
    int am = tid >> 3, ak = (tid & 7) * 4;
    int vk = tid >> 4, vn4 = (tid & 15) * 4;

    float4 ra[4], rv[2];
#pragma unroll
    for (int r = 0; r < 4; r++)
        ra[r] = *(const float4*)&A[(size_t)(bm + am + 32 * r) * LSEQ + ak];
#pragma unroll
    for (int r = 0; r < 2; r++)
        rv[r] = *(const float4*)&V[(size_t)(vk + 16 * r) * DH + vn4];

    for (int k0 = 0; k0 < LSEQ; k0 += 32) {
#pragma unroll
        for (int r = 0; r < 4; r++)
            *(uint4*)&As[am + 32 * r][ak] =
                make_uint4(f2tf(ra[r].x), f2tf(ra[r].y), f2tf(ra[r].z), f2tf(ra[r].w));
#pragma unroll
        for (int r = 0; r < 2; r++)
            *(uint4*)&Bs[vk + 16 * r][vn4] =
                make_uint4(f2tf(rv[r].x), f2tf(rv[r].y), f2tf(rv[r].z), f2tf(rv[r].w));
        __syncthreads();
        if (k0 + 32 < LSEQ) {
#pragma unroll
            for (int r = 0; r < 4; r++)
                ra[r] = *(const float4*)&A[(size_t)(bm + am + 32 * r) * LSEQ + k0 + 32 + ak];
#pragma unroll
            for (int r = 0; r < 2; r++)
                rv[r] = *(const float4*)&V[(size_t)(k0 + 32 + vk + 16 * r) * DH + vn4];
        }
#pragma unroll
        for (int ks = 0; ks < 32; ks += 8) {
            unsigned af[2][4], bf[4][2];
#pragma unroll
            for (int mi = 0; mi < 2; mi++) {
                int r0 = wm + 16 * mi + g;
                af[mi][0] = As[r0][ks + i4];
                af[mi][1] = As[r0 + 8][ks + i4];
                af[mi][2] = As[r0][ks + i4 + 4];
                af[mi][3] = As[r0 + 8][ks + i4 + 4];
            }
#pragma unroll
            for (int ni = 0; ni < 4; ni++) {
                bf[ni][0] = Bs[ks + i4][wn + 8 * ni + g];
                bf[ni][1] = Bs[ks + i4 + 4][wn + 8 * ni + g];
            }
#pragma unroll
            for (int mi = 0; mi < 2; mi++)
#pragma unroll
                for (int ni = 0; ni < 4; ni++)
                    mma_tf32(acc[mi][ni], af[mi], bf[ni]);
        }
        __syncthreads();
    }

    int b = z >> 4, h = z & 15;
#pragma unroll
    for (int mi = 0; mi < 2; mi++) {
#pragma unroll
        for (int ni = 0; ni < 4; ni++) {
#pragma unroll
            for (int e = 0; e < 4; e++) {
                int q = bm + wm + 16 * mi + g + (e >> 1) * 8;
                int n = wn + 8 * ni + 2 * i4 + (e & 1);
                g_O[((size_t)(b * LSEQ + q)) * DMODEL + h * 64 + n] = acc[mi][ni][e];
            }
        }
    }
}

// ====== g_O += T @ posV (tf32 mma; M=65536, N=64, K=288 padded) ============
__global__ void __launch_bounds__(256) gemm_tposv_t(const float* __restrict__ posV)
{
    __shared__ __align__(16) unsigned As[128][36];
    __shared__ __align__(16) unsigned Bs[32][72];
    int bm = blockIdx.x * 128;
    int tid = threadIdx.x;
    int warp = tid >> 5, lane = tid & 31;
    int wm = warp * 16;
    int g = lane >> 2, i4 = lane & 3;

    float acc[8][4] = {};
    int am = tid >> 3, ak = (tid & 7) * 4;
    int vk = tid >> 4, vn4 = (tid & 15) * 4;

    for (int k0 = 0; k0 < TP; k0 += 32) {
#pragma unroll
        for (int r = 0; r < 4; r++) {
            float4 v = *(const float4*)&g_T[(size_t)(bm + am + 32 * r) * TP + k0 + ak];
            *(uint4*)&As[am + 32 * r][ak] =
                make_uint4(f2tf(v.x), f2tf(v.y), f2tf(v.z), f2tf(v.w));
        }
#pragma unroll
        for (int r = 0; r < 2; r++) {
            int k = k0 + vk + 16 * r;
            float4 w = make_float4(0.f, 0.f, 0.f, 0.f);
            if (k < NPOS) w = *(const float4*)&posV[(size_t)k * DH + vn4];
            *(uint4*)&Bs[vk + 16 * r][vn4] =
                make_uint4(f2tf(w.x), f2tf(w.y), f2tf(w.z), f2tf(w.w));
        }
        __syncthreads();
#pragma unroll
        for (int ks = 0; ks < 32; ks += 8) {
            unsigned af[4], bf[8][2];
            int r0 = wm + g;
            af[0] = As[r0][ks + i4];
            af[1] = As[r0 + 8][ks + i4];
            af[2] = As[r0][ks + i4 + 4];
            af[3] = As[r0 + 8][ks + i4 + 4];
#pragma unroll
            for (int ni = 0; ni < 8; ni++) {
                bf[ni][0] = Bs[ks + i4][8 * ni + g];
                bf[ni][1] = Bs[ks + i4 + 4][8 * ni + g];
            }
#pragma unroll
            for (int ni = 0; ni < 8; ni++)
                mma_tf32(acc[ni], af, bf[ni]);
        }
        __syncthreads();
    }

#pragma unroll
    for (int ni = 0; ni < 8; ni++) {
#pragma unroll
        for (int e = 0; e < 4; e++) {
            int r = bm + wm + g + (e >> 1) * 8;
            int z = r >> 10, q = r & 1023;
            int b = z >> 4, h = z & 15;
            int n = 8 * ni + 2 * i4 + (e & 1);
            size_t idx = ((size_t)(b * LSEQ + q)) * DMODEL + h * 64 + n;
            g_O[idx] += acc[ni][e];
        }
    }
}

// ---------------------------------------------------------------------------
extern "C" void kernel_launch(void* const* d_in, const int* in_sizes, int n_in,
                              void* d_out, int out_size)
{
    const float* x    = (const float*)d_in[0];
    const float* pad  = (const float*)d_in[1];
    const float* Wq   = (const float*)d_in[2];
    const float* bq   = (const float*)d_in[3];
    const float* Wk   = (const float*)d_in[4];
    const float* bk   = (const float*)d_in[5];
    const float* Wv   = (const float*)d_in[6];
    const float* bv   = (const float*)d_in[7];
    const float* Wo   = (const float*)d_in[8];
    const float* bo   = (const float*)d_in[9];
    const float* posK = (const float*)d_in[10];
    const float* posV = (const float*)d_in[11];
    float* out = (float*)d_out;

    float *Qp, *Kp, *Vp, *Op;
    cudaGetSymbolAddress((void**)&Qp, g_Q);
    cudaGetSymbolAddress((void**)&Kp, g_K);
    cudaGetSymbolAddress((void**)&Vp, g_V);
    cudaGetSymbolAddress((void**)&Op, g_O);

    dim3 g128(DMODEL / 128, MROW / 128);   // (8, 32)
    gemm_proj_t<true><<<g128, 256>>>(x, Wq, bq, Qp, DMODEL, DMODEL);
    gemm_proj_t<true><<<g128, 256>>>(x, Wk, bk, Kp, DMODEL, DMODEL);
    gemm_proj_t<true><<<g128, 256>>>(x, Wv, bv, Vp, DMODEL, DMODEL);

    gemm_qposk_t<<<dim3(3, ROWS / 128), 256>>>(posK);
    attn_scores_t<<<dim3(8, 8, BH), 256>>>(pad);
    softmax_T<<<ROWS, 256>>>();
    gemm_av_t<<<dim3(8, BH), 256>>>();
    gemm_tposv_t<<<dim3(ROWS / 128), 256>>>(posV);

    gemm_proj_t<false><<<g128, 256>>>(Op, Wo, bo, out, DMODEL, DMODEL);
}